// round 3
// baseline (speedup 1.0000x reference)
#include <cuda_runtime.h>
#include <math.h>

// Problem constants
#define CC      512
#define BB      16
#define TT      60
#define NP      196
#define NHEADS  4
#define HD      128
#define CLIPL   6
#define NFRAMES 36
#define TOPK    6
#define TOPM    12

// Output layout (flat float32):
//   [0]       audio_top_k        (16,36,512)
//   [294912]  visual_patch_top_m (16,36,12,512)
//   [3833856] visual_patch_feat  (16,432,512)  (identical bytes to top_m)
#define OFF1 294912
#define OFF2 3833856

// Block-role layout (single fused kernel)
#define NB_GATHER 576
#define NB_Q      32
#define NB_R      8
#define NB_S      196
#define NB_PID    1
#define NB_TOTAL  (NB_GATHER + NB_Q + NB_R + NB_S + NB_PID)   // 813

// Scratch + sync state (device globals; zero-initialized at module load,
// counters restored to zero by last-consumer reset each launch)
__device__ float g_q[CC];
__device__ float g_r[NHEADS * CC];
__device__ float g_scores[NHEADS * NP];
__device__ int   g_pid;
__device__ int   c_q,  c_qd;    // q produced (32) / consumed by r (8)
__device__ int   c_r,  c_rd;    // r produced (8)  / consumed by scores (196)
__device__ int   c_s;           // scores produced (196), sole consumer = pid block
__device__ int   c_p,  c_pd;    // pid produced (1) / consumed by gather (576)

// ---- sync helpers -----------------------------------------------------------
__device__ __forceinline__ void spin_wait(volatile int* p, int target) {
    if (threadIdx.x == 0) {
        while (*p < target) __nanosleep(64);
    }
    __syncthreads();
    __threadfence();            // acquire: order subsequent data reads
}
__device__ __forceinline__ void signal_done(int* c) {
    __syncthreads();
    __threadfence();            // release: data visible before count
    if (threadIdx.x == 0) atomicAdd(c, 1);
}
// Last of n consumers resets producer counter (all n already passed the wait).
__device__ __forceinline__ void consume_reset(int* cdone, int n, int* cprod) {
    if (threadIdx.x == 0) {
        if (atomicAdd(cdone, 1) == n - 1) { *cprod = 0; *cdone = 0; }
    }
}

// ---- fused kernel -----------------------------------------------------------
__global__ void __launch_bounds__(128)
fused_kernel(const float* __restrict__ audio,
             const float* __restrict__ patch,
             const float* __restrict__ qst,
             const int*   __restrict__ topk,
             const float* __restrict__ in_w,
             const float* __restrict__ in_b,
             float*       __restrict__ out) {
    __shared__ float sh[4 * 128];       // q-vec cache / score reduction
    __shared__ float shw[NP];           // pid weights
    __shared__ float s_mx[NHEADS], s_inv[NHEADS];
    __shared__ int   s_pid;

    const int bid = blockIdx.x;
    const int t   = threadIdx.x;
    const int warp = t >> 5, lane = t & 31;

    // =========================== GATHER blocks ==============================
    if (bid < NB_GATHER) {
        const int b = bid / NFRAMES, f = bid % NFRAMES;
        const int seg   = topk[b * TOPK + f / CLIPL];
        const int frame = seg * CLIPL + (f % CLIPL);

        const float4* a4 = (const float4*)audio;
        const float4* p4 = (const float4*)patch;
        float4*       o4 = (float4*)out;

        // audio_top_k[b,f,:]  — independent of pid, issue immediately
        o4[(size_t)bid * 128 + t] = a4[((size_t)b * TT + frame) * 128 + t];

        // wait for pid, then broadcast patch row pid to both outputs
        spin_wait(&c_p, 1);
        const int pid = g_pid;
        const float4 p = p4[(((size_t)b * TT + frame) * NP + pid) * 128 + t];
        size_t base1 = OFF1 / 4 + (size_t)bid * TOPM * 128 + t;
        size_t base2 = OFF2 / 4 + (size_t)bid * TOPM * 128 + t;
        #pragma unroll
        for (int m = 0; m < TOPM; m++) {
            o4[base1 + (size_t)m * 128] = p;
            o4[base2 + (size_t)m * 128] = p;
        }
        consume_reset(&c_pd, NB_GATHER, &c_p);
        return;
    }

    // ============================= Q blocks =================================
    // q[row] = Wq[row,:] . qst[0,:] + bq[row].  32 blocks x 4 warps x 4 rows.
    if (bid < NB_GATHER + NB_Q) {
        const int qb = bid - NB_GATHER;
        const float4* x4 = (const float4*)qst;     // batch 0
        #pragma unroll
        for (int rr = 0; rr < 4; rr++) {
            const int row = (qb * 4 + warp) * 4 + rr;
            const float4* w4 = (const float4*)(in_w + (size_t)row * CC);
            float acc = 0.f;
            #pragma unroll
            for (int i = lane; i < CC / 4; i += 32) {
                float4 a = w4[i], x = x4[i];
                acc += a.x * x.x + a.y * x.y + a.z * x.z + a.w * x.w;
            }
            #pragma unroll
            for (int o = 16; o; o >>= 1) acc += __shfl_down_sync(0xffffffffu, acc, o);
            if (lane == 0) g_q[row] = acc + in_b[row];
        }
        signal_done(&c_q);
        return;
    }

    // ============================= R blocks =================================
    // r_h[c] = sum_j Wk[h*128+j, c] * q[h*128+j]   (row-major coalesced)
    if (bid < NB_GATHER + NB_Q + NB_R) {
        const int rid = bid - NB_GATHER - NB_Q;       // 0..7
        const int h = rid >> 1, cb = (rid & 1) * 256;

        spin_wait(&c_q, NB_Q);
        consume_reset(&c_qd, NB_R, &c_q);

        sh[t] = g_q[h * HD + t];
        __syncthreads();

        const float* Wk = in_w + (size_t)(CC + h * HD) * CC;
        float a0 = 0.f, a1 = 0.f;
        #pragma unroll 4
        for (int j = 0; j < HD; j++) {
            const float* row = Wk + (size_t)j * CC;
            const float qj = sh[j];
            a0 += row[cb + t]       * qj;
            a1 += row[cb + 128 + t] * qj;
        }
        g_r[h * CC + cb + t]       = a0;
        g_r[h * CC + cb + 128 + t] = a1;
        signal_done(&c_r);
        return;
    }

    // ============================ SCORE blocks ==============================
    // score[h][n] = scale * (r_h . x_n)   at (b=0, f=0).  Block per patch n.
    if (bid < NB_GATHER + NB_Q + NB_R + NB_S) {
        const int n = bid - NB_GATHER - NB_Q - NB_R;

        spin_wait(&c_r, NB_R);
        consume_reset(&c_rd, NB_S, &c_r);

        const int f0 = topk[0] * CLIPL;     // frame_ids[0,0]
        const float* x = patch + (((size_t)f0 * NP) + n) * CC;
        float xv[4];
        #pragma unroll
        for (int i = 0; i < 4; i++) xv[i] = x[t + i * 128];
        float acc[NHEADS] = {0.f, 0.f, 0.f, 0.f};
        #pragma unroll
        for (int h = 0; h < NHEADS; h++)
            #pragma unroll
            for (int i = 0; i < 4; i++)
                acc[h] += g_r[h * CC + t + i * 128] * xv[i];

        #pragma unroll
        for (int h = 0; h < NHEADS; h++) sh[h * 128 + t] = acc[h];
        __syncthreads();
        float v = sh[warp * 128 + lane] + sh[warp * 128 + lane + 32] +
                  sh[warp * 128 + lane + 64] + sh[warp * 128 + lane + 96];
        #pragma unroll
        for (int o = 16; o; o >>= 1) v += __shfl_down_sync(0xffffffffu, v, o);
        if (lane == 0)
            g_scores[warp * NP + n] = 0.08838834764831845f * v;  // 1/sqrt(128)
        signal_done(&c_s);
        return;
    }

    // ============================= PID block ================================
    {
        spin_wait(&c_s, NB_S);
        if (t == 0) c_s = 0;                 // sole consumer resets

        // per-head softmax stats (warp per head)
        float m = -1e30f;
        for (int n = lane; n < NP; n += 32) m = fmaxf(m, g_scores[warp * NP + n]);
        #pragma unroll
        for (int o = 16; o; o >>= 1) m = fmaxf(m, __shfl_xor_sync(0xffffffffu, m, o));
        float s = 0.f;
        for (int n = lane; n < NP; n += 32) s += expf(g_scores[warp * NP + n] - m);
        #pragma unroll
        for (int o = 16; o; o >>= 1) s += __shfl_xor_sync(0xffffffffu, s, o);
        if (lane == 0) { s_mx[warp] = m; s_inv[warp] = 1.f / s; }
        if (t == 0) s_pid = -1;
        __syncthreads();

        // mean-over-heads softmax weights
        for (int n = t; n < NP; n += 128) {
            float acc = 0.f;
            #pragma unroll
            for (int h = 0; h < NHEADS; h++)
                acc += expf(g_scores[h * NP + n] - s_mx[h]) * s_inv[h];
            shw[n] = acc * 0.25f;
        }
        __syncthreads();

        // pid = max index among top-12 weights (stable-argsort tie-break)
        for (int n = t; n < NP; n += 128) {
            const float wn = shw[n];
            int cnt = 0;
            for (int m2 = 0; m2 < NP; m2++)
                cnt += (shw[m2] > wn) || (shw[m2] == wn && m2 > n);
            if (cnt < TOPM) atomicMax(&s_pid, n);
        }
        __syncthreads();
        if (t == 0) g_pid = s_pid;
        signal_done(&c_p);
    }
}

// ---------------------------------------------------------------------------
extern "C" void kernel_launch(void* const* d_in, const int* in_sizes, int n_in,
                              void* d_out, int out_size) {
    const float* audio = (const float*)d_in[0];   // (16,60,512)
    const float* patch = (const float*)d_in[1];   // (16,60,196,512)
    const float* qst   = (const float*)d_in[2];   // (16,512)
    const int*   topk  = (const int*)  d_in[3];   // (16,1,6)
    const float* in_w  = (const float*)d_in[4];   // (1536,512)
    const float* in_b  = (const float*)d_in[5];   // (1536,)
    float* out = (float*)d_out;

    fused_kernel<<<NB_TOTAL, 128>>>(audio, patch, qst, topk, in_w, in_b, out);
}

// round 4
// speedup vs baseline: 1.1098x; 1.1098x over previous
#include <cuda_runtime.h>
#include <math.h>

// Problem constants
#define CC      512
#define BB      16
#define TT      60
#define NP      196
#define NHEADS  4
#define HD      128
#define CLIPL   6
#define NFRAMES 36
#define TOPK    6
#define TOPM    12

// Output layout (flat float32):
//   [0]       audio_top_k        (16,36,512)
//   [294912]  visual_patch_top_m (16,36,12,512)
//   [3833856] visual_patch_feat  (16,432,512)  (identical bytes)
#define OFF1 294912
#define OFF2 3833856

// k_qr block roles
#define NB_R      16     // 4 heads x 4 col-slices (each recomputes its head's q)
#define NB_AUDIO  72     // 72 x 8 (b,f) rows
#define NB_PREF   4      // L2 prefetch of score-phase patch rows
#define NB_QR     (NB_R + NB_AUDIO + NB_PREF)   // 92

// Scratch (device globals)
__device__ float g_r[NHEADS * CC];
__device__ int   g_pid;

// ===========================================================================
// K1: r + audio gather + L2 prefetch.  No internal sync needed: each r-block
//     recomputes the 128 q values of its own head from Wq.
// ===========================================================================
__global__ void __launch_bounds__(128)
k_qr(const float* __restrict__ audio,
     const float* __restrict__ patch,
     const float* __restrict__ qst,
     const int*   __restrict__ topk,
     const float* __restrict__ in_w,
     const float* __restrict__ in_b,
     float*       __restrict__ out) {
    const int bid  = blockIdx.x;
    const int t    = threadIdx.x;
    const int warp = t >> 5, lane = t & 31;

    // ----------------- r blocks: q_h (recomputed) then r slice -------------
    if (bid < NB_R) {
        __shared__ float sh_q[HD];
        const int h  = bid >> 2;            // head 0..3
        const int cb = (bid & 3) * 128;     // col slice

        // q_h[row_local] = Wq[h*128+row_local,:] . qst[0,:] + bq
        // warp per 32 rows, two rows in flight to hide reduce latency
        const float4* x4 = (const float4*)qst;   // batch 0
        float4 xv[4];
        #pragma unroll
        for (int i = 0; i < 4; i++) xv[i] = x4[lane + 32 * i];
        for (int rbase = warp * 32; rbase < warp * 32 + 32; rbase += 2) {
            const int row0 = h * HD + rbase, row1 = row0 + 1;
            const float4* w0 = (const float4*)(in_w + (size_t)row0 * CC);
            const float4* w1 = (const float4*)(in_w + (size_t)row1 * CC);
            float a0 = 0.f, a1 = 0.f;
            #pragma unroll
            for (int i = 0; i < 4; i++) {
                float4 aa = w0[lane + 32 * i], bb = w1[lane + 32 * i];
                a0 += aa.x * xv[i].x + aa.y * xv[i].y + aa.z * xv[i].z + aa.w * xv[i].w;
                a1 += bb.x * xv[i].x + bb.y * xv[i].y + bb.z * xv[i].z + bb.w * xv[i].w;
            }
            #pragma unroll
            for (int o = 16; o; o >>= 1) {
                a0 += __shfl_down_sync(0xffffffffu, a0, o);
                a1 += __shfl_down_sync(0xffffffffu, a1, o);
            }
            if (lane == 0) {
                sh_q[rbase]     = a0 + in_b[row0];
                sh_q[rbase + 1] = a1 + in_b[row1];
            }
        }
        __syncthreads();

        // r_h[cb+t] = sum_j Wk[h*128+j, cb+t] * q_h[j]   (coalesced over t)
        const float* Wk = in_w + (size_t)(CC + h * HD) * CC + cb + t;
        float acc = 0.f;
        #pragma unroll 8
        for (int j = 0; j < HD; j++)
            acc += Wk[(size_t)j * CC] * sh_q[j];
        g_r[h * CC + cb + t] = acc;
        return;
    }

    // ----------------- audio gather blocks (pid-independent) ---------------
    if (bid < NB_R + NB_AUDIO) {
        const int ab = bid - NB_R;
        const float4* a4 = (const float4*)audio;
        float4*       o4 = (float4*)out;
        #pragma unroll
        for (int k = 0; k < 8; k++) {
            const int bf = ab * 8 + k;
            const int b = bf / NFRAMES, f = bf % NFRAMES;
            const int seg   = topk[b * TOPK + f / CLIPL];
            const int frame = seg * CLIPL + (f % CLIPL);
            o4[(size_t)bf * 128 + t] = a4[((size_t)b * TT + frame) * 128 + t];
        }
        return;
    }

    // ----------------- prefetch blocks: warm L2 for k_scorepid -------------
    {
        const int pb = bid - NB_R - NB_AUDIO;           // 0..3
        const int f0 = topk[0] * CLIPL;
        const char* base = (const char*)(patch + (size_t)f0 * NP * CC);
        const int total_lines = NP * CC * 4 / 128;      // 3136 x 128B
        for (int i = pb * 128 + t; i < total_lines; i += NB_PREF * 128) {
            const char* p = base + (size_t)i * 128;
            asm volatile("prefetch.global.L2 [%0];" :: "l"(p));
        }
    }
}

// ===========================================================================
// K2: scores (196 patches x 4 heads) + softmax + top-12 select.  One block.
// ===========================================================================
__global__ void __launch_bounds__(1024)
k_scorepid(const float* __restrict__ patch, const int* __restrict__ topk) {
    __shared__ float sh_r[NHEADS * CC];      // 8KB
    __shared__ float s_sc[NHEADS * NP];      // scores
    __shared__ float s_w[NP];
    __shared__ float s_mx[NHEADS], s_inv[NHEADS];
    __shared__ int   s_pid;

    const int t = threadIdx.x;               // 0..1023
    const int warp = t >> 5, lane = t & 31;

    // load r into shared
    sh_r[t] = g_r[t];
    sh_r[t + 1024] = g_r[t + 1024];
    if (t == 0) s_pid = -1;
    __syncthreads();

    // scores: warp per patch, strided
    const int f0 = topk[0] * CLIPL;
    const float4* p4 = (const float4*)(patch + (size_t)f0 * NP * CC);
    const float4* r4 = (const float4*)sh_r;
    for (int n = warp; n < NP; n += 32) {
        float4 xv[4];
        #pragma unroll
        for (int i = 0; i < 4; i++) xv[i] = p4[(size_t)n * 128 + lane + 32 * i];
        float acc[NHEADS] = {0.f, 0.f, 0.f, 0.f};
        #pragma unroll
        for (int h = 0; h < NHEADS; h++)
            #pragma unroll
            for (int i = 0; i < 4; i++) {
                float4 rv = r4[h * 128 + lane + 32 * i];
                acc[h] += rv.x * xv[i].x + rv.y * xv[i].y +
                          rv.z * xv[i].z + rv.w * xv[i].w;
            }
        #pragma unroll
        for (int h = 0; h < NHEADS; h++) {
            float v = acc[h];
            #pragma unroll
            for (int o = 16; o; o >>= 1) v += __shfl_down_sync(0xffffffffu, v, o);
            if (lane == 0) s_sc[h * NP + n] = 0.08838834764831845f * v;
        }
    }
    __syncthreads();

    // per-head softmax stats (warp per head)
    if (warp < NHEADS) {
        float m = -1e30f;
        for (int n = lane; n < NP; n += 32) m = fmaxf(m, s_sc[warp * NP + n]);
        #pragma unroll
        for (int o = 16; o; o >>= 1) m = fmaxf(m, __shfl_xor_sync(0xffffffffu, m, o));
        float s = 0.f;
        for (int n = lane; n < NP; n += 32) s += expf(s_sc[warp * NP + n] - m);
        #pragma unroll
        for (int o = 16; o; o >>= 1) s += __shfl_xor_sync(0xffffffffu, s, o);
        if (lane == 0) { s_mx[warp] = m; s_inv[warp] = 1.f / s; }
    }
    __syncthreads();

    // mean-over-heads softmax weights
    if (t < NP) {
        float acc = 0.f;
        #pragma unroll
        for (int h = 0; h < NHEADS; h++)
            acc += expf(s_sc[h * NP + t] - s_mx[h]) * s_inv[h];
        s_w[t] = acc * 0.25f;
    }
    __syncthreads();

    // pid = max index among top-12 (stable-argsort tie-break)
    if (t < NP) {
        const float wn = s_w[t];
        int cnt = 0;
        for (int m = 0; m < NP; m++)
            cnt += (s_w[m] > wn) || (s_w[m] == wn && m > t);
        if (cnt < TOPM) atomicMax(&s_pid, t);
    }
    __syncthreads();
    if (t == 0) g_pid = s_pid;
}

// ===========================================================================
// K3: pid-dependent broadcast (27MB store stream)
// ===========================================================================
__global__ void __launch_bounds__(128)
k_bcast(const float* __restrict__ patch, const int* __restrict__ topk,
        float* __restrict__ out) {
    const int bf = blockIdx.x;              // 0..575
    const int t  = threadIdx.x;             // 0..127
    const int b = bf / NFRAMES, f = bf % NFRAMES;
    const int seg   = topk[b * TOPK + f / CLIPL];
    const int frame = seg * CLIPL + (f % CLIPL);
    const int pid = g_pid;

    const float4* p4 = (const float4*)patch;
    float4*       o4 = (float4*)out;
    const float4 p = p4[(((size_t)b * TT + frame) * NP + pid) * 128 + t];

    size_t base1 = OFF1 / 4 + (size_t)bf * TOPM * 128 + t;
    size_t base2 = OFF2 / 4 + (size_t)bf * TOPM * 128 + t;
    #pragma unroll
    for (int m = 0; m < TOPM; m++) {
        o4[base1 + (size_t)m * 128] = p;
        o4[base2 + (size_t)m * 128] = p;
    }
}

// ---------------------------------------------------------------------------
extern "C" void kernel_launch(void* const* d_in, const int* in_sizes, int n_in,
                              void* d_out, int out_size) {
    const float* audio = (const float*)d_in[0];   // (16,60,512)
    const float* patch = (const float*)d_in[1];   // (16,60,196,512)
    const float* qst   = (const float*)d_in[2];   // (16,512)
    const int*   topk  = (const int*)  d_in[3];   // (16,1,6)
    const float* in_w  = (const float*)d_in[4];   // (1536,512)
    const float* in_b  = (const float*)d_in[5];   // (1536,)
    float* out = (float*)d_out;

    k_qr<<<NB_QR, 128>>>(audio, patch, qst, topk, in_w, in_b, out);
    k_scorepid<<<1, 1024>>>(patch, topk);
    k_bcast<<<BB * NFRAMES, 128>>>(patch, topk, out);
}

// round 5
// speedup vs baseline: 1.4521x; 1.3085x over previous
#include <cuda_runtime.h>
#include <math.h>

// Problem constants
#define CC      512
#define BB      16
#define TT      60
#define NP      196
#define NHEADS  4
#define HD      128
#define CLIPL   6
#define NFRAMES 36
#define TOPK    6
#define TOPM    12

// Output layout (flat float32):
//   [0]       audio_top_k        (16,36,512)
//   [294912]  visual_patch_top_m (16,36,12,512)
//   [3833856] visual_patch_feat  (16,432,512)  (identical bytes)
#define OFF1 294912
#define OFF2 3833856

// k_q block roles
#define NB_QROWS  128    // 128 blocks x 4 warps = 512 rows (warp per row)
#define NB_AUDIO  72     // audio gather, 8 (b,f) rows each
#define NB_PREF   24     // L2 prefetch: Wk (1MB) + score-phase patch rows (400KB)
#define NB_Q      (NB_QROWS + NB_AUDIO + NB_PREF)   // 224

// Scratch (device globals)
__device__ float g_q[CC];
__device__ float g_r[NHEADS * CC];
__device__ int   g_pid;

// ===========================================================================
// K1: q (warp per row) + audio gather + L2 prefetch for later kernels
// ===========================================================================
__global__ void __launch_bounds__(128)
k_q(const float* __restrict__ audio,
    const float* __restrict__ patch,
    const float* __restrict__ qst,
    const int*   __restrict__ topk,
    const float* __restrict__ in_w,
    const float* __restrict__ in_b,
    float*       __restrict__ out) {
    const int bid  = blockIdx.x;
    const int t    = threadIdx.x;
    const int warp = t >> 5, lane = t & 31;

    // ----------------- q rows: one warp per output row ---------------------
    if (bid < NB_QROWS) {
        const int row = bid * 4 + warp;           // 0..511
        const float4* x4 = (const float4*)qst;    // batch 0
        const float4* w4 = (const float4*)(in_w + (size_t)row * CC);
        float acc = 0.f;
        #pragma unroll
        for (int i = 0; i < 4; i++) {
            float4 a = w4[lane + 32 * i];
            float4 x = x4[lane + 32 * i];
            acc += a.x * x.x + a.y * x.y + a.z * x.z + a.w * x.w;
        }
        #pragma unroll
        for (int o = 16; o; o >>= 1) acc += __shfl_down_sync(0xffffffffu, acc, o);
        if (lane == 0) g_q[row] = acc + in_b[row];
        return;
    }

    // ----------------- audio gather (pid-independent) ----------------------
    if (bid < NB_QROWS + NB_AUDIO) {
        const int ab = bid - NB_QROWS;
        const float4* a4 = (const float4*)audio;
        float4*       o4 = (float4*)out;
        #pragma unroll
        for (int k = 0; k < 8; k++) {
            const int bf = ab * 8 + k;
            const int b = bf / NFRAMES, f = bf % NFRAMES;
            const int seg   = topk[b * TOPK + f / CLIPL];
            const int frame = seg * CLIPL + (f % CLIPL);
            o4[(size_t)bf * 128 + t] = a4[((size_t)b * TT + frame) * 128 + t];
        }
        return;
    }

    // ----------------- prefetch: Wk (rows 512..1023) + score patch rows ----
    {
        const int pb  = bid - NB_QROWS - NB_AUDIO;     // 0..23
        const int tid = pb * 128 + t;                  // 0..3071
        const int NTH = NB_PREF * 128;

        // Wk: 1MB = 8192 x 128B lines
        const char* wk = (const char*)(in_w + (size_t)CC * CC);
        for (int i = tid; i < 8192; i += NTH) {
            asm volatile("prefetch.global.L2 [%0];" :: "l"(wk + (size_t)i * 128));
        }
        // patch rows for scores: 196*512*4B = 3136 x 128B lines
        const int f0 = topk[0] * CLIPL;
        const char* pr = (const char*)(patch + (size_t)f0 * NP * CC);
        for (int i = tid; i < 3136; i += NTH) {
            asm volatile("prefetch.global.L2 [%0];" :: "l"(pr + (size_t)i * 128));
        }
    }
}

// ===========================================================================
// K2: r_h[c] = sum_j Wk[h*128+j, c] * q[h*128+j]
//     64 blocks = 4 heads x 16 col-slices (32 cols).  256 thr = 8 warps,
//     j split across warps (16 each, MLP 16), smem cross-warp reduce.
// ===========================================================================
__global__ void __launch_bounds__(256)
k_r(const float* __restrict__ in_w) {
    __shared__ float sh_q[HD];
    __shared__ float sh_p[8][32];

    const int h  = blockIdx.x >> 4;            // head
    const int cb = (blockIdx.x & 15) * 32;     // col base
    const int t  = threadIdx.x;
    const int warp = t >> 5, lane = t & 31;

    if (t < HD) sh_q[t] = g_q[h * HD + t];
    __syncthreads();

    const float* Wk = in_w + (size_t)(CC + h * HD + warp * 16) * CC + cb + lane;
    float acc = 0.f;
    #pragma unroll
    for (int j = 0; j < 16; j++)
        acc += Wk[(size_t)j * CC] * sh_q[warp * 16 + j];
    sh_p[warp][lane] = acc;
    __syncthreads();

    if (t < 32) {
        float s = 0.f;
        #pragma unroll
        for (int w = 0; w < 8; w++) s += sh_p[w][t];
        g_r[h * CC + cb + t] = s;
    }
}

// ===========================================================================
// K3: scores (196 patches x 4 heads) + softmax + top-12 select.  One block.
// ===========================================================================
__global__ void __launch_bounds__(1024)
k_scorepid(const float* __restrict__ patch, const int* __restrict__ topk) {
    __shared__ float sh_r[NHEADS * CC];
    __shared__ float s_sc[NHEADS * NP];
    __shared__ float s_w[NP];
    __shared__ float s_mx[NHEADS], s_inv[NHEADS];
    __shared__ int   s_pid;

    const int t = threadIdx.x;
    const int warp = t >> 5, lane = t & 31;

    sh_r[t] = g_r[t];
    sh_r[t + 1024] = g_r[t + 1024];
    if (t == 0) s_pid = -1;
    __syncthreads();

    // scores: warp per patch, strided over 32 warps (L2-warm from prefetch)
    const int f0 = topk[0] * CLIPL;
    const float4* p4 = (const float4*)(patch + (size_t)f0 * NP * CC);
    const float4* r4 = (const float4*)sh_r;
    for (int n = warp; n < NP; n += 32) {
        float4 xv[4];
        #pragma unroll
        for (int i = 0; i < 4; i++) xv[i] = p4[(size_t)n * 128 + lane + 32 * i];
        float acc[NHEADS] = {0.f, 0.f, 0.f, 0.f};
        #pragma unroll
        for (int h = 0; h < NHEADS; h++)
            #pragma unroll
            for (int i = 0; i < 4; i++) {
                float4 rv = r4[h * 128 + lane + 32 * i];
                acc[h] += rv.x * xv[i].x + rv.y * xv[i].y +
                          rv.z * xv[i].z + rv.w * xv[i].w;
            }
        #pragma unroll
        for (int h = 0; h < NHEADS; h++) {
            float v = acc[h];
            #pragma unroll
            for (int o = 16; o; o >>= 1) v += __shfl_down_sync(0xffffffffu, v, o);
            if (lane == 0) s_sc[h * NP + n] = 0.08838834764831845f * v;
        }
    }
    __syncthreads();

    // per-head softmax stats (warp per head)
    if (warp < NHEADS) {
        float m = -1e30f;
        for (int n = lane; n < NP; n += 32) m = fmaxf(m, s_sc[warp * NP + n]);
        #pragma unroll
        for (int o = 16; o; o >>= 1) m = fmaxf(m, __shfl_xor_sync(0xffffffffu, m, o));
        float s = 0.f;
        for (int n = lane; n < NP; n += 32) s += expf(s_sc[warp * NP + n] - m);
        #pragma unroll
        for (int o = 16; o; o >>= 1) s += __shfl_xor_sync(0xffffffffu, s, o);
        if (lane == 0) { s_mx[warp] = m; s_inv[warp] = 1.f / s; }
    }
    __syncthreads();

    // mean-over-heads softmax weights
    if (t < NP) {
        float acc = 0.f;
        #pragma unroll
        for (int h = 0; h < NHEADS; h++)
            acc += expf(s_sc[h * NP + t] - s_mx[h]) * s_inv[h];
        s_w[t] = acc * 0.25f;
    }
    __syncthreads();

    // pid = max index among top-12 (stable-argsort tie-break)
    if (t < NP) {
        const float wn = s_w[t];
        int cnt = 0;
        for (int m = 0; m < NP; m++)
            cnt += (s_w[m] > wn) || (s_w[m] == wn && m > t);
        if (cnt < TOPM) atomicMax(&s_pid, t);
    }
    __syncthreads();
    if (t == 0) g_pid = s_pid;
}

// ===========================================================================
// K4: pid-dependent broadcast (27MB streaming store)
// ===========================================================================
__global__ void __launch_bounds__(128)
k_bcast(const float* __restrict__ patch, const int* __restrict__ topk,
        float* __restrict__ out) {
    const int bf = blockIdx.x;              // 0..575
    const int t  = threadIdx.x;             // 0..127
    const int b = bf / NFRAMES, f = bf % NFRAMES;
    const int seg   = topk[b * TOPK + f / CLIPL];
    const int frame = seg * CLIPL + (f % CLIPL);
    const int pid = g_pid;

    const float4* p4 = (const float4*)patch;
    float4*       o4 = (float4*)out;
    const float4 p = p4[(((size_t)b * TT + frame) * NP + pid) * 128 + t];

    size_t base1 = OFF1 / 4 + (size_t)bf * TOPM * 128 + t;
    size_t base2 = OFF2 / 4 + (size_t)bf * TOPM * 128 + t;
    #pragma unroll
    for (int m = 0; m < TOPM; m++) {
        __stcs(&o4[base1 + (size_t)m * 128], p);
        __stcs(&o4[base2 + (size_t)m * 128], p);
    }
}

// ---------------------------------------------------------------------------
extern "C" void kernel_launch(void* const* d_in, const int* in_sizes, int n_in,
                              void* d_out, int out_size) {
    const float* audio = (const float*)d_in[0];   // (16,60,512)
    const float* patch = (const float*)d_in[1];   // (16,60,196,512)
    const float* qst   = (const float*)d_in[2];   // (16,512)
    const int*   topk  = (const int*)  d_in[3];   // (16,1,6)
    const float* in_w  = (const float*)d_in[4];   // (1536,512)
    const float* in_b  = (const float*)d_in[5];   // (1536,)
    float* out = (float*)d_out;

    k_q<<<NB_Q, 128>>>(audio, patch, qst, topk, in_w, in_b, out);
    k_r<<<64, 256>>>(in_w);
    k_scorepid<<<1, 1024>>>(patch, topk);
    k_bcast<<<BB * NFRAMES, 128>>>(patch, topk, out);
}